// round 12
// baseline (speedup 1.0000x reference)
#include <cuda_runtime.h>
#include <cstdint>

#define B_DIM 256
#define N_DIM 64
#define T_DIM 4096
#define H_DIM 16
#define TS    256   // t-tile per CTA
#define CH    64    // t-chunk width (4 chunks per tile)
#define SBC   72    // x chunk SMEM row stride (floats): mod 32 = 8 -> conflict-free
// Scratch (device global — no allocation allowed)
__device__ float g_energy[B_DIM * N_DIM];

// ======================= helpers =======================
__device__ __forceinline__ uint32_t smem_u32(const void* p) {
    uint32_t a;
    asm("{ .reg .u64 t; cvta.to.shared.u64 t, %1; cvt.u32.u64 %0, t; }" : "=r"(a) : "l"(p));
    return a;
}
__device__ __forceinline__ void cp16(uint32_t smem_dst, const void* gsrc) {
    asm volatile("cp.async.cg.shared.global [%0], [%1], 16;" :: "r"(smem_dst), "l"(gsrc) : "memory");
}
#define CP_COMMIT() asm volatile("cp.async.commit_group;" ::: "memory")
#define CP_WAIT(n)  asm volatile("cp.async.wait_group %0;" :: "n"(n) : "memory")

__device__ __forceinline__ uint32_t f2tf32(float f) {
    uint32_t r;
    asm("cvt.rna.tf32.f32 %0, %1;" : "=r"(r) : "f"(f));
    return r;
}
__device__ __forceinline__ void mma_tf32(float& d0, float& d1, float& d2, float& d3,
                                         uint32_t a0, uint32_t a1, uint32_t a2, uint32_t a3,
                                         uint32_t b0, uint32_t b1) {
    asm volatile(
        "mma.sync.aligned.m16n8k8.row.col.f32.tf32.tf32.f32 "
        "{%0,%1,%2,%3},{%4,%5,%6,%7},{%8,%9},{%0,%1,%2,%3};"
        : "+f"(d0), "+f"(d1), "+f"(d2), "+f"(d3)
        : "r"(a0), "r"(a1), "r"(a2), "r"(a3), "r"(b0), "r"(b1));
}

// ---------------------------------------------------------------------------
// Kernel 1: energy[b,n] = var(x[b,n,:]) over T. One warp per (b,n) row.
// ---------------------------------------------------------------------------
__global__ __launch_bounds__(256) void energy_kernel(const float* __restrict__ x) {
    int gw   = (blockIdx.x * blockDim.x + threadIdx.x) >> 5;
    int lane = threadIdx.x & 31;
    if (gw >= B_DIM * N_DIM) return;
    const float4* row = reinterpret_cast<const float4*>(x + (size_t)gw * T_DIM);
    float s = 0.f, ss = 0.f;
#pragma unroll
    for (int k = 0; k < 32; k++) {
        float4 v = row[k * 32 + lane];
        s  += (v.x + v.y) + (v.z + v.w);
        ss += v.x * v.x + v.y * v.y + v.z * v.z + v.w * v.w;
    }
#pragma unroll
    for (int o = 16; o > 0; o >>= 1) {
        s  += __shfl_xor_sync(0xffffffffu, s, o);
        ss += __shfl_xor_sync(0xffffffffu, ss, o);
    }
    if (lane == 0) {
        float m = s * (1.f / T_DIM);
        g_energy[gw] = fmaf(-m, m, ss * (1.f / T_DIM));
    }
}

// ---------------------------------------------------------------------------
// Kernel 2: attn weights (rank-1 logits + softmax) -> attn_out [b][i][j].
// ---------------------------------------------------------------------------
__global__ __launch_bounds__(64) void attn_kernel(const float* __restrict__ Wq,
                                                  const float* __restrict__ bq,
                                                  const float* __restrict__ Wk,
                                                  const float* __restrict__ bk,
                                                  float* __restrict__ attn_out) {
    __shared__ float e[N_DIM];
    __shared__ float wsm[N_DIM * 65];
    int b = blockIdx.x;
    int i = threadIdx.x;
    e[i] = g_energy[b * N_DIM + i];

    float c0 = 0.f, c1 = 0.f, c2 = 0.f, c3 = 0.f;
#pragma unroll
    for (int h = 0; h < H_DIM; h++) {
        float wq = Wq[h], bqh = bq[h], wk = Wk[h], bkh = bk[h];
        c0 = fmaf(wq, wk, c0);
        c1 = fmaf(wq, bkh, c1);
        c2 = fmaf(bqh, wk, c2);
        c3 = fmaf(bqh, bkh, c3);
    }
    __syncthreads();

    const float scale = 0.25f;
    float ei = e[i];
    float l[N_DIM];
    float mx = -1e30f;
#pragma unroll
    for (int j = 0; j < N_DIM; j++) {
        float ej = e[j];
        float v = scale * (ei * ej * c0 + ei * c1 + ej * c2 + c3);
        if (j == i) v = -1e9f;
        l[j] = v;
        mx = fmaxf(mx, v);
    }
    float sum = 0.f;
#pragma unroll
    for (int j = 0; j < N_DIM; j++) {
        float w = __expf(l[j] - mx);
        l[j] = w;
        sum += w;
    }
    float inv = 1.f / sum;
#pragma unroll
    for (int j = 0; j < N_DIM; j++)
        wsm[i * 65 + j] = l[j] * inv;
    __syncthreads();

    float* ao = attn_out + (size_t)b * N_DIM * N_DIM;
#pragma unroll
    for (int k = 0; k < N_DIM; k++)
        ao[k * 64 + i] = wsm[k * 65 + i];  // w[k][i], coalesced
}

// ---------------------------------------------------------------------------
// Kernel 3: out[b,i,t] = sum_j w[b,i,j]*x[b,j,t] + x[b,i,t]
// 3 CTAs/SM: xs-only SMEM (72 KB), A-fragments via direct LDG from attn_out
// (L2-hot, shared by 16 CTAs/batch), <=84 regs. 8 warps = 4 i-bands (16 rows)
// x 2 t-halves. 4 x-chunks cp.async'd up-front; B frags raw fp32 bits (tf32
// HW truncation); residual exact fp32. Reverse batch order for L2 tail reuse.
// ---------------------------------------------------------------------------
__global__ __launch_bounds__(256, 3) void out_kernel(const float* __restrict__ x,
                                                     const float* __restrict__ w,
                                                     float* __restrict__ out) {
    extern __shared__ float smem[];
    float* xs = smem;                       // 4 x [64][SBC]

    int b    = B_DIM - 1 - (int)blockIdx.y;  // reverse batch order (L2 reuse)
    int tile = blockIdx.x;
    int tid  = threadIdx.x;
    int wid  = tid >> 5;
    int lane = tid & 31;

    const float* xb = x + (size_t)b * N_DIM * T_DIM + (size_t)tile * TS;

    // Prefetch all 4 x chunks (groups 0..3), 4 cp16 per thread per chunk.
#pragma unroll
    for (int ch = 0; ch < 4; ch++) {
        float* xc = xs + ch * N_DIM * SBC;
#pragma unroll
        for (int k = 0; k < 4; k++) {
            int f  = k * 256 + tid;
            int j  = f >> 4;
            int c4 = f & 15;
            cp16(smem_u32(xc + j * SBC + c4 * 4),
                 xb + (size_t)j * T_DIM + ch * CH + c4 * 4);
        }
        CP_COMMIT();
    }

    int i0 = (wid & 3) * 16;   // i band (16 rows)
    int th = wid >> 2;         // t half (0/1): [th*32, +32) within chunk
    int r  = lane >> 2;        // 0..7
    int c  = lane & 3;         // 0..3

    // A fragments by direct LDG from w (attn_out): 8 ksteps x 4 regs = 32.
    // 16 CTAs per batch share this 16KB region -> L2/L1 hot.
    const float* wsrc = w + (size_t)b * N_DIM * N_DIM;
    uint32_t a[8][4];
#pragma unroll
    for (int ks = 0; ks < 8; ks++) {
        int j0 = ks * 8 + c;
        a[ks][0] = f2tf32(__ldg(wsrc + (i0 + r) * 64 + j0));
        a[ks][1] = f2tf32(__ldg(wsrc + (i0 + r + 8) * 64 + j0));
        a[ks][2] = f2tf32(__ldg(wsrc + (i0 + r) * 64 + j0 + 4));
        a[ks][3] = f2tf32(__ldg(wsrc + (i0 + r + 8) * 64 + j0 + 4));
    }

    float* ob = out + (size_t)b * N_DIM * T_DIM + (size_t)tile * TS;

#pragma unroll
    for (int ch = 0; ch < 4; ch++) {
        if (ch == 0) CP_WAIT(3);
        else if (ch == 1) CP_WAIT(2);
        else if (ch == 2) CP_WAIT(1);
        else CP_WAIT(0);
        __syncthreads();

        const float* xc = xs + ch * N_DIM * SBC;
#pragma unroll
        for (int nt = 0; nt < 4; nt++) {
            int t0 = th * 32 + nt * 8;
            float d0 = 0.f, d1 = 0.f, d2 = 0.f, d3 = 0.f;
#pragma unroll
            for (int ks = 0; ks < 8; ks++) {
                // Raw fp32 bits -> tf32 truncation in HW.
                uint32_t b0 = __float_as_uint(xc[(ks * 8 + c) * SBC + t0 + r]);
                uint32_t b1 = __float_as_uint(xc[(ks * 8 + c + 4) * SBC + t0 + r]);
                mma_tf32(d0, d1, d2, d3,
                         a[ks][0], a[ks][1], a[ks][2], a[ks][3], b0, b1);
            }
            // Epilogue: exact fp32 residual + coalesced STG.64.
            int tcol = t0 + 2 * c;
            int row0 = i0 + r, row1 = row0 + 8;
            float2 res0 = *reinterpret_cast<const float2*>(xc + row0 * SBC + tcol);
            float2 res1 = *reinterpret_cast<const float2*>(xc + row1 * SBC + tcol);
            float2 o0 = make_float2(d0 + res0.x, d1 + res0.y);
            float2 o1 = make_float2(d2 + res1.x, d3 + res1.y);
            int tg = ch * CH + tcol;
            *reinterpret_cast<float2*>(ob + (size_t)row0 * T_DIM + tg) = o0;
            *reinterpret_cast<float2*>(ob + (size_t)row1 * T_DIM + tg) = o1;
        }
        if (ch < 3) __syncthreads();
    }
}

extern "C" void kernel_launch(void* const* d_in, const int* in_sizes, int n_in,
                              void* d_out, int out_size) {
    const float* x  = (const float*)d_in[0];
    const float* Wq = (const float*)d_in[1];
    const float* bq = (const float*)d_in[2];
    const float* Wk = (const float*)d_in[3];
    const float* bk = (const float*)d_in[4];

    float* out = (float*)d_out;
    float* attn_out = out + (size_t)B_DIM * N_DIM * T_DIM;

    const int smem_bytes = 4 * N_DIM * SBC * (int)sizeof(float);  // 73728
    cudaFuncSetAttribute(out_kernel, cudaFuncAttributeMaxDynamicSharedMemorySize, smem_bytes);

    energy_kernel<<<(B_DIM * N_DIM * 32) / 256, 256>>>(x);
    attn_kernel<<<B_DIM, 64>>>(Wq, bq, Wk, bk, attn_out);
    dim3 grid(T_DIM / TS, B_DIM);
    out_kernel<<<grid, 256, smem_bytes>>>(x, attn_out, out);
}

// round 14
// speedup vs baseline: 1.1503x; 1.1503x over previous
#include <cuda_runtime.h>
#include <cstdint>

#define B_DIM 256
#define N_DIM 64
#define T_DIM 4096
#define H_DIM 16
#define TS    256   // t-tile per CTA
#define CH    64    // t-chunk width; chunk p owned by warp-pair p
#define SBC   72    // x chunk SMEM row stride (floats): mod 32 = 8 -> conflict-free
#define SW    68    // w SMEM row stride (floats): 4r+c banks, conflict-free

// Scratch (device global — no allocation allowed)
__device__ float g_energy[B_DIM * N_DIM];

// ======================= helpers =======================
__device__ __forceinline__ uint32_t smem_u32(const void* p) {
    uint32_t a;
    asm("{ .reg .u64 t; cvta.to.shared.u64 t, %1; cvt.u32.u64 %0, t; }" : "=r"(a) : "l"(p));
    return a;
}
__device__ __forceinline__ void cp16(uint32_t smem_dst, const void* gsrc) {
    asm volatile("cp.async.cg.shared.global [%0], [%1], 16;" :: "r"(smem_dst), "l"(gsrc) : "memory");
}
#define CP_COMMIT() asm volatile("cp.async.commit_group;" ::: "memory")
#define CP_WAIT(n)  asm volatile("cp.async.wait_group %0;" :: "n"(n) : "memory")
#define BAR_PAIR(id) asm volatile("bar.sync %0, 64;" :: "r"(id) : "memory")

__device__ __forceinline__ uint32_t f2tf32(float f) {
    uint32_t r;
    asm("cvt.rna.tf32.f32 %0, %1;" : "=r"(r) : "f"(f));
    return r;
}
__device__ __forceinline__ void mma_tf32(float& d0, float& d1, float& d2, float& d3,
                                         uint32_t a0, uint32_t a1, uint32_t a2, uint32_t a3,
                                         uint32_t b0, uint32_t b1) {
    asm volatile(
        "mma.sync.aligned.m16n8k8.row.col.f32.tf32.tf32.f32 "
        "{%0,%1,%2,%3},{%4,%5,%6,%7},{%8,%9},{%0,%1,%2,%3};"
        : "+f"(d0), "+f"(d1), "+f"(d2), "+f"(d3)
        : "r"(a0), "r"(a1), "r"(a2), "r"(a3), "r"(b0), "r"(b1));
}

// ---------------------------------------------------------------------------
// Kernel 1: energy[b,n] = var(x[b,n,:]) over T. One warp per (b,n) row.
// ---------------------------------------------------------------------------
__global__ __launch_bounds__(256) void energy_kernel(const float* __restrict__ x) {
    int gw   = (blockIdx.x * blockDim.x + threadIdx.x) >> 5;
    int lane = threadIdx.x & 31;
    if (gw >= B_DIM * N_DIM) return;
    const float4* row = reinterpret_cast<const float4*>(x + (size_t)gw * T_DIM);
    float s = 0.f, ss = 0.f;
#pragma unroll
    for (int k = 0; k < 32; k++) {
        float4 v = row[k * 32 + lane];
        s  += (v.x + v.y) + (v.z + v.w);
        ss += v.x * v.x + v.y * v.y + v.z * v.z + v.w * v.w;
    }
#pragma unroll
    for (int o = 16; o > 0; o >>= 1) {
        s  += __shfl_xor_sync(0xffffffffu, s, o);
        ss += __shfl_xor_sync(0xffffffffu, ss, o);
    }
    if (lane == 0) {
        float m = s * (1.f / T_DIM);
        g_energy[gw] = fmaf(-m, m, ss * (1.f / T_DIM));
    }
}

// ---------------------------------------------------------------------------
// Kernel 2: attn weights (rank-1 logits + softmax) -> attn_out [b][i][j].
// ---------------------------------------------------------------------------
__global__ __launch_bounds__(64) void attn_kernel(const float* __restrict__ Wq,
                                                  const float* __restrict__ bq,
                                                  const float* __restrict__ Wk,
                                                  const float* __restrict__ bk,
                                                  float* __restrict__ attn_out) {
    __shared__ float e[N_DIM];
    __shared__ float wsm[N_DIM * 65];
    int b = blockIdx.x;
    int i = threadIdx.x;
    e[i] = g_energy[b * N_DIM + i];

    float c0 = 0.f, c1 = 0.f, c2 = 0.f, c3 = 0.f;
#pragma unroll
    for (int h = 0; h < H_DIM; h++) {
        float wq = Wq[h], bqh = bq[h], wk = Wk[h], bkh = bk[h];
        c0 = fmaf(wq, wk, c0);
        c1 = fmaf(wq, bkh, c1);
        c2 = fmaf(bqh, wk, c2);
        c3 = fmaf(bqh, bkh, c3);
    }
    __syncthreads();

    const float scale = 0.25f;
    float ei = e[i];
    float l[N_DIM];
    float mx = -1e30f;
#pragma unroll
    for (int j = 0; j < N_DIM; j++) {
        float ej = e[j];
        float v = scale * (ei * ej * c0 + ei * c1 + ej * c2 + c3);
        if (j == i) v = -1e9f;
        l[j] = v;
        mx = fmaxf(mx, v);
    }
    float sum = 0.f;
#pragma unroll
    for (int j = 0; j < N_DIM; j++) {
        float w = __expf(l[j] - mx);
        l[j] = w;
        sum += w;
    }
    float inv = 1.f / sum;
#pragma unroll
    for (int j = 0; j < N_DIM; j++)
        wsm[i * 65 + j] = l[j] * inv;
    __syncthreads();

    float* ao = attn_out + (size_t)b * N_DIM * N_DIM;
#pragma unroll
    for (int k = 0; k < N_DIM; k++)
        ao[k * 64 + i] = wsm[k * 65 + i];  // w[k][i], coalesced
}

// ---------------------------------------------------------------------------
// Kernel 3: out[b,i,t] = sum_j w[b,i,j]*x[b,j,t] + x[b,i,t]
// CTA: (t-tile 256, batch). 4 warp-PAIRS; pair p owns chunk p ([64 j][64 t]),
// loads it with its own 64 threads, waits its own cp.async group, syncs via
// named barrier — NO CTA-wide barriers in the mainloop. Each warp: 2 i-band
// accumulator chains (dual MMA streams), B frags raw fp32 bits (tf32 HW
// truncation), residual exact fp32. w via cp.async + one CTA sync.
// ---------------------------------------------------------------------------
__global__ __launch_bounds__(256, 2) void out_kernel(const float* __restrict__ x,
                                                     const float* __restrict__ w,
                                                     float* __restrict__ out) {
    extern __shared__ float smem[];
    float* xs = smem;                       // 4 x [64][SBC]
    float* ws = smem + 4 * N_DIM * SBC;     // [64][SW]

    int b    = B_DIM - 1 - (int)blockIdx.y;  // reverse batch order (L2 reuse)
    int tile = blockIdx.x;
    int tid  = threadIdx.x;
    int wid  = tid >> 5;
    int lane = tid & 31;
    int p    = wid >> 1;        // warp-pair = chunk index (0..3)
    int ih   = wid & 1;         // i half within pair
    int pt   = tid & 63;        // thread index within pair

    const float* xb = x + (size_t)b * N_DIM * T_DIM + (size_t)tile * TS;
    const float* wsrc = w + (size_t)b * N_DIM * N_DIM;

    // Group 0 (all threads): w — 1024 float4, 4 per thread.
#pragma unroll
    for (int k = 0; k < 4; k++) {
        int f  = k * 256 + tid;   // float4 index
        int i  = f >> 4;          // row (16 float4 per row)
        int c4 = f & 15;
        cp16(smem_u32(ws + i * SW + c4 * 4), wsrc + f * 4);
    }
    CP_COMMIT();

    // Group 1 (per pair): own chunk p — 1024 float4 by 64 threads, 16 each.
    {
        float* xc = xs + p * N_DIM * SBC;
        const float* xg = xb + p * CH;
#pragma unroll
        for (int k = 0; k < 16; k++) {
            int f  = k * 64 + pt;
            int j  = f >> 4;
            int c4 = f & 15;
            cp16(smem_u32(xc + j * SBC + c4 * 4),
                 xg + (size_t)j * T_DIM + c4 * 4);
        }
        CP_COMMIT();
    }

    int i0 = ih * 32;
    int r  = lane >> 2;        // 0..7
    int c  = lane & 3;         // 0..3

    // Wait w (own chunk may still be in flight), CTA sync, build A frags.
    CP_WAIT(1);
    __syncthreads();
    uint32_t a[2][8][4];
#pragma unroll
    for (int band = 0; band < 2; band++) {
        int ib = i0 + band * 16;
#pragma unroll
        for (int ks = 0; ks < 8; ks++) {
            int j0 = ks * 8 + c;
            a[band][ks][0] = f2tf32(ws[(ib + r) * SW + j0]);
            a[band][ks][1] = f2tf32(ws[(ib + r + 8) * SW + j0]);
            a[band][ks][2] = f2tf32(ws[(ib + r) * SW + j0 + 4]);
            a[band][ks][3] = f2tf32(ws[(ib + r + 8) * SW + j0 + 4]);
        }
    }

    // Wait own chunk; named-barrier the pair (chunk written only by pair).
    CP_WAIT(0);
    BAR_PAIR(p + 1);

    const float* xc = xs + p * N_DIM * SBC;
    float* ob = out + (size_t)b * N_DIM * T_DIM + (size_t)tile * TS + p * CH;

    // Mainloop: 8 nt x 8 ks, dual accumulator chains, no barriers.
#pragma unroll
    for (int nt = 0; nt < 8; nt++) {
        int t0 = nt * 8;
        float d[2][4];
#pragma unroll
        for (int band = 0; band < 2; band++)
#pragma unroll
            for (int q = 0; q < 4; q++) d[band][q] = 0.f;
#pragma unroll
        for (int ks = 0; ks < 8; ks++) {
            // Raw fp32 bits -> tf32 truncation in HW.
            uint32_t b0 = __float_as_uint(xc[(ks * 8 + c) * SBC + t0 + r]);
            uint32_t b1 = __float_as_uint(xc[(ks * 8 + c + 4) * SBC + t0 + r]);
            mma_tf32(d[0][0], d[0][1], d[0][2], d[0][3],
                     a[0][ks][0], a[0][ks][1], a[0][ks][2], a[0][ks][3], b0, b1);
            mma_tf32(d[1][0], d[1][1], d[1][2], d[1][3],
                     a[1][ks][0], a[1][ks][1], a[1][ks][2], a[1][ks][3], b0, b1);
        }
        // Epilogue: exact fp32 residual + coalesced STG.64.
        int tcol = t0 + 2 * c;
#pragma unroll
        for (int band = 0; band < 2; band++) {
            int row0 = i0 + band * 16 + r, row1 = row0 + 8;
            float2 res0 = *reinterpret_cast<const float2*>(xc + row0 * SBC + tcol);
            float2 res1 = *reinterpret_cast<const float2*>(xc + row1 * SBC + tcol);
            float2 o0 = make_float2(d[band][0] + res0.x, d[band][1] + res0.y);
            float2 o1 = make_float2(d[band][2] + res1.x, d[band][3] + res1.y);
            *reinterpret_cast<float2*>(ob + (size_t)row0 * T_DIM + tcol) = o0;
            *reinterpret_cast<float2*>(ob + (size_t)row1 * T_DIM + tcol) = o1;
        }
    }
}

extern "C" void kernel_launch(void* const* d_in, const int* in_sizes, int n_in,
                              void* d_out, int out_size) {
    const float* x  = (const float*)d_in[0];
    const float* Wq = (const float*)d_in[1];
    const float* bq = (const float*)d_in[2];
    const float* Wk = (const float*)d_in[3];
    const float* bk = (const float*)d_in[4];

    float* out = (float*)d_out;
    float* attn_out = out + (size_t)B_DIM * N_DIM * T_DIM;

    const int smem_bytes = (4 * N_DIM * SBC + N_DIM * SW) * (int)sizeof(float);  // 91136
    cudaFuncSetAttribute(out_kernel, cudaFuncAttributeMaxDynamicSharedMemorySize, smem_bytes);

    energy_kernel<<<(B_DIM * N_DIM * 32) / 256, 256>>>(x);
    attn_kernel<<<B_DIM, 64>>>(Wq, bq, Wk, bk, attn_out);
    dim3 grid(T_DIM / TS, B_DIM);
    out_kernel<<<grid, 256, smem_bytes>>>(x, attn_out, out);
}